// round 7
// baseline (speedup 1.0000x reference)
#include <cuda_runtime.h>
#include <cuda_bf16.h>
#include <cstdint>
#include <cstddef>

// ---------------------------------------------------------------------------
// ComplexSpatialAttentionModule, sm_100 PTX target: mma.sync m16n8k16 bf16
// flash attention (single-pass online softmax, cp.async double-buffered K/V),
// 512 threads/CTA: 8 row-groups x 2 channel-halves (split-N P.V for 4
// warps/SMSP latency hiding). Projections: f32x2 SIMT emitting bf16 splits.
// ---------------------------------------------------------------------------

#define BATCH 4
#define CCH   256
#define DQK   32
#define NTOK  4096

typedef unsigned long long u64t;

// ----- packed f32x2 helpers (projection kernels) -----
#define FMA2(d, a, b, c) \
    asm("fma.rn.f32x2 %0, %1, %2, %3;" : "=l"(d) : "l"(a), "l"(b), "l"(c))
#define BCAST2(out, f) \
    asm("mov.b64 %0, {%1, %1};" : "=l"(out) : "r"(__float_as_uint(f)))
#define UNPACK2(lo, hi, v) \
    asm("mov.b64 {%0, %1}, %2;" : "=r"(lo), "=r"(hi) : "l"(v))
union F4U2 { float4 f; u64t u[2]; };
__device__ __forceinline__ float lo_f(u64t v) {
    unsigned int l, h; UNPACK2(l, h, v); return __uint_as_float(l);
}
__device__ __forceinline__ float hi_f(u64t v) {
    unsigned int l, h; UNPACK2(l, h, v); return __uint_as_float(h);
}

// ----- bf16 split/pack helpers -----
__device__ __forceinline__ uint32_t pk2(float lo, float hi) {
    uint32_t u;
    asm("cvt.rn.bf16x2.f32 %0, %1, %2;" : "=r"(u) : "f"(hi), "f"(lo));
    return u;
}
__device__ __forceinline__ void bsp(float x, float& h, float& l) {
    __nv_bfloat16 hb = __float2bfloat16(x);
    h = __bfloat162float(hb);
    l = x - h;
}

// ----- scratch (device globals) -----
__device__ __align__(16) uint32_t g_qh[BATCH * NTOK * 16];
__device__ __align__(16) uint32_t g_ql[BATCH * NTOK * 16];
__device__ __align__(16) uint32_t g_kh[BATCH * NTOK * 16];
__device__ __align__(16) uint32_t g_kl[BATCH * NTOK * 16];
__device__ __align__(16) uint32_t g_vh[BATCH * CCH * (NTOK / 2)];
__device__ __align__(16) uint32_t g_vl[BATCH * CCH * (NTOK / 2)];
__device__ float g_ao[BATCH * CCH * NTOK];

#define DST_Q   0
#define DST_K   1
#define DST_V   2
#define DST_OUT 3

// ---------------------------------------------------------------------------
// Projection: out[o][n] = sum_c w[o][c] x[c][n] + b[o]. 64x64 tile, f32x2.
// ---------------------------------------------------------------------------
template <int OC, int DST, bool RES>
__global__ __launch_bounds__(256) void proj_kernel(
    const float* __restrict__ xparam, const float* __restrict__ w,
    const float* __restrict__ bias, float* __restrict__ outparam)
{
    constexpr int IC = CCH;
    __shared__ float wt[16][64];
    __shared__ float xs[16][64];

    const int b = blockIdx.z;
    const float* xin = (DST == DST_OUT) ? (const float*)g_ao : xparam;
    const float* xb = xin + (size_t)b * IC * NTOK;

    const int ntile = blockIdx.x * 64;
    const int otile = blockIdx.y * 64;
    const int t  = threadIdx.x;
    const int og = t & 15, ng = t >> 4;
    const int o0 = og * 4, n0 = ng * 4;

    u64t acc2[4][2];
#pragma unroll
    for (int i = 0; i < 4; i++) { acc2[i][0] = 0ull; acc2[i][1] = 0ull; }

    for (int ct = 0; ct < IC; ct += 16) {
#pragma unroll
        for (int i = 0; i < 4; i++) {
            int idx = t + i * 256;
            int o = idx >> 4, cc = idx & 15;
            float val = 0.f;
            if (otile + o < OC) val = w[(size_t)(otile + o) * IC + ct + cc];
            wt[cc][o] = val;
        }
#pragma unroll
        for (int i = 0; i < 4; i++) {
            int idx = t + i * 256;
            int cc = idx >> 6, n = idx & 63;
            xs[cc][n] = xb[(size_t)(ct + cc) * NTOK + ntile + n];
        }
        __syncthreads();
#pragma unroll
        for (int cc = 0; cc < 16; cc++) {
            F4U2 w4, x4;
            w4.f = *(const float4*)&wt[cc][o0];
            x4.f = *(const float4*)&xs[cc][n0];
            float wv4[4] = {w4.f.x, w4.f.y, w4.f.z, w4.f.w};
            u64t wb[4];
#pragma unroll
            for (int oi = 0; oi < 4; oi++) BCAST2(wb[oi], wv4[oi]);
#pragma unroll
            for (int oi = 0; oi < 4; oi++) {
                FMA2(acc2[oi][0], wb[oi], x4.u[0], acc2[oi][0]);
                FMA2(acc2[oi][1], wb[oi], x4.u[1], acc2[oi][1]);
            }
        }
        __syncthreads();
    }

    float vals[4][4];
#pragma unroll
    for (int oi = 0; oi < 4; oi++) {
        vals[oi][0] = lo_f(acc2[oi][0]); vals[oi][1] = hi_f(acc2[oi][0]);
        vals[oi][2] = lo_f(acc2[oi][1]); vals[oi][3] = hi_f(acc2[oi][1]);
    }

    if (DST == DST_Q || DST == DST_K) {
        if (o0 < DQK) {
            uint32_t* gh = ((DST == DST_Q) ? g_qh : g_kh) + (size_t)b * NTOK * 16;
            uint32_t* gl = ((DST == DST_Q) ? g_ql : g_kl) + (size_t)b * NTOK * 16;
            float bv[4] = {bias[o0], bias[o0 + 1], bias[o0 + 2], bias[o0 + 3]};
#pragma unroll
            for (int ni = 0; ni < 4; ni++) {
                float h[4], l[4];
#pragma unroll
                for (int oi = 0; oi < 4; oi++) bsp(vals[oi][ni] + bv[oi], h[oi], l[oi]);
                size_t widx = (size_t)(ntile + n0 + ni) * 16 + (o0 >> 1);
                *(uint2*)(gh + widx) = make_uint2(pk2(h[0], h[1]), pk2(h[2], h[3]));
                *(uint2*)(gl + widx) = make_uint2(pk2(l[0], l[1]), pk2(l[2], l[3]));
            }
        }
    } else if (DST == DST_V) {
#pragma unroll
        for (int oi = 0; oi < 4; oi++) {
            int o = otile + o0 + oi;
            float bv = bias[o];
            float h[4], l[4];
#pragma unroll
            for (int ni = 0; ni < 4; ni++) bsp(vals[oi][ni] + bv, h[ni], l[ni]);
            size_t widx = ((size_t)b * CCH + o) * (NTOK / 2) + ((ntile + n0) >> 1);
            *(uint2*)(g_vh + widx) = make_uint2(pk2(h[0], h[1]), pk2(h[2], h[3]));
            *(uint2*)(g_vl + widx) = make_uint2(pk2(l[0], l[1]), pk2(l[2], l[3]));
        }
    } else {
        float* ob = outparam + (size_t)b * OC * NTOK;
        const float* rb = xparam + (size_t)b * OC * NTOK;
#pragma unroll
        for (int oi = 0; oi < 4; oi++) {
            int o = otile + o0 + oi;
            float bv = bias[o];
            size_t off = (size_t)o * NTOK + ntile + n0;
            float4 r;
            r.x = vals[oi][0] + bv; r.y = vals[oi][1] + bv;
            r.z = vals[oi][2] + bv; r.w = vals[oi][3] + bv;
            if (RES) {
                float4 rr = *(const float4*)&rb[off];
                r.x += rr.x; r.y += rr.y; r.z += rr.z; r.w += rr.w;
            }
            *(float4*)&ob[off] = r;
        }
    }
}

// ---------------------------------------------------------------------------
// mma.sync / ldmatrix / cp.async helpers
// ---------------------------------------------------------------------------
__device__ __forceinline__ uint32_t smem_u32(const void* p) {
    uint32_t a;
    asm("{ .reg .u64 t; cvta.to.shared.u64 t, %1; cvt.u32.u64 %0, t; }"
        : "=r"(a) : "l"(p));
    return a;
}
__device__ __forceinline__ void ldsm4(uint32_t addr, uint32_t& r0, uint32_t& r1,
                                      uint32_t& r2, uint32_t& r3) {
    asm volatile("ldmatrix.sync.aligned.m8n8.x4.shared.b16 {%0,%1,%2,%3}, [%4];"
                 : "=r"(r0), "=r"(r1), "=r"(r2), "=r"(r3) : "r"(addr));
}
__device__ __forceinline__ void mmabf(float* d, const uint32_t* a,
                                      uint32_t b0, uint32_t b1) {
    asm volatile(
        "mma.sync.aligned.m16n8k16.row.col.f32.bf16.bf16.f32 "
        "{%0,%1,%2,%3}, {%4,%5,%6,%7}, {%8,%9}, {%0,%1,%2,%3};"
        : "+f"(d[0]), "+f"(d[1]), "+f"(d[2]), "+f"(d[3])
        : "r"(a[0]), "r"(a[1]), "r"(a[2]), "r"(a[3]), "r"(b0), "r"(b1));
}
__device__ __forceinline__ void cp16(uint32_t dst, const void* src) {
    asm volatile("cp.async.cg.shared.global [%0], [%1], 16;"
                 :: "r"(dst), "l"(src) : "memory");
}
#define CP_COMMIT() asm volatile("cp.async.commit_group;" ::: "memory")
#define CP_WAIT1()  asm volatile("cp.async.wait_group 1;" ::: "memory")

// ---------------------------------------------------------------------------
// Attention SMEM layout (bytes):
//   QH 0, QL 10240           (128 rows x 80B)
//   K buf0 20480, buf1 30720 (64 rows x 80B, hi +0, lo +5120)
//   V buf0 40960, buf1 114688 (256 rows x 144B, hi +0, lo +36864)
// ---------------------------------------------------------------------------
#define SM_QH 0
#define SM_QL 10240
#define KB0   20480
#define KB1   30720
#define KLOFF 5120
#define VB0   40960
#define VB1   114688
#define VLOFF 36864
#define ATTN_SMEM 188416

// 512 threads: K 512 cp16 (1/thread), V 4096 cp16 (8/thread)
__device__ __forceinline__ void issue_tile(uint32_t sb, int buf, int nc, int t,
    const uint4* gkh, const uint4* gkl, const uint4* gvh, const uint4* gvl)
{
    const uint32_t kb = sb + (buf ? KB1 : KB0);
    const uint32_t vb = sb + (buf ? VB1 : VB0);
    const int krow = t >> 3, kq = (t >> 1) & 3, ksel = t & 1;
    cp16(kb + (ksel ? KLOFF : 0) + krow * 80 + kq * 16,
         (ksel ? gkl : gkh) + (size_t)(nc + krow) * 4 + kq);
    const int vr = t >> 3, vq = t & 7;
    const int nq = nc >> 3;
#pragma unroll
    for (int i = 0; i < 4; i++) {
        int row = vr + i * 64;
        cp16(vb + row * 144 + vq * 16,         gvh + (size_t)row * 512 + nq + vq);
        cp16(vb + VLOFF + row * 144 + vq * 16, gvl + (size_t)row * 512 + nq + vq);
    }
}

__global__ __launch_bounds__(512) void attn_mma_kernel()
{
    extern __shared__ __align__(16) char smem[];
    const int t = threadIdx.x, lane = t & 31, w = t >> 5;
    const int rg = w & 7;        // row group: q rows rg*16..rg*16+15
    const int hf = w >> 3;       // channel half: hf*128..hf*128+127
    const int b = blockIdx.y, q0 = blockIdx.x * 128;
    const uint32_t sb = smem_u32(smem);

    const uint4* gkh = (const uint4*)g_kh + (size_t)b * NTOK * 4;
    const uint4* gkl = (const uint4*)g_kl + (size_t)b * NTOK * 4;
    const uint4* gvh = (const uint4*)g_vh + (size_t)b * CCH * 512;
    const uint4* gvl = (const uint4*)g_vl + (size_t)b * CCH * 512;

    // ---- Q tile -> SMEM (hi/lo), threads 0-255 ----
    if (t < 256) {
        int row = t >> 1;
        size_t gidx = ((size_t)b * NTOK + q0 + row) * 4 + (t & 1) * 2;
        const uint4* sh = (const uint4*)g_qh + gidx;
        const uint4* sl = (const uint4*)g_ql + gidx;
        uint4* dh = (uint4*)(smem + SM_QH + row * 80 + (t & 1) * 32);
        uint4* dl = (uint4*)(smem + SM_QL + row * 80 + (t & 1) * 32);
        dh[0] = sh[0]; dh[1] = sh[1];
        dl[0] = sl[0]; dl[1] = sl[1];
    }
    issue_tile(sb, 0, 0, t, gkh, gkl, gvh, gvl);
    CP_COMMIT();
    __syncthreads();

    // ---- preload Q A-fragments ----
    const int a_row  = (lane & 7) + (lane & 8);
    const int a_kofs = (lane & 16) ? 8 : 0;
    const int b_row  = (lane & 7) + ((lane & 16) ? 8 : 0);
    const int b_kofs = (lane & 8);

    uint32_t qa_h[2][4], qa_l[2][4];
#pragma unroll
    for (int kc = 0; kc < 2; kc++) {
        uint32_t byteoff = (uint32_t)(rg * 16 + a_row) * 80 + (kc * 16 + a_kofs) * 2;
        ldsm4(sb + SM_QH + byteoff, qa_h[kc][0], qa_h[kc][1], qa_h[kc][2], qa_h[kc][3]);
        ldsm4(sb + SM_QL + byteoff, qa_l[kc][0], qa_l[kc][1], qa_l[kc][2], qa_l[kc][3]);
    }

    float M0 = -1e30f, M1 = -1e30f, sum0 = 0.f, sum1 = 0.f;
    float o[16][4];
#pragma unroll
    for (int i = 0; i < 16; i++)
#pragma unroll
        for (int j = 0; j < 4; j++) o[i][j] = 0.f;

    // ================= single-pass online flash loop =================
    for (int ti = 0; ti < 64; ti++) {
        if (ti < 63) issue_tile(sb, (ti + 1) & 1, (ti + 1) * 64, t, gkh, gkl, gvh, gvl);
        CP_COMMIT();
        CP_WAIT1();
        __syncthreads();

        const uint32_t kb = sb + ((ti & 1) ? KB1 : KB0);
        const uint32_t vb = sb + ((ti & 1) ? VB1 : VB0);

        // ---- S = Q.K^T (3-term), duplicated across halves ----
        float sfr[8][4];
#pragma unroll
        for (int i = 0; i < 8; i++)
#pragma unroll
            for (int j = 0; j < 4; j++) sfr[i][j] = 0.f;

#pragma unroll
        for (int nfp = 0; nfp < 4; nfp++)
#pragma unroll
            for (int kc = 0; kc < 2; kc++) {
                uint32_t boff = (uint32_t)(nfp * 16 + b_row) * 80 + (kc * 16 + b_kofs) * 2;
                uint32_t h0, h1, h2, h3, l0, l1, l2, l3;
                ldsm4(kb + boff, h0, h1, h2, h3);
                ldsm4(kb + KLOFF + boff, l0, l1, l2, l3);
                mmabf(sfr[2 * nfp],     qa_h[kc], h0, h1);
                mmabf(sfr[2 * nfp + 1], qa_h[kc], h2, h3);
                mmabf(sfr[2 * nfp],     qa_h[kc], l0, l1);
                mmabf(sfr[2 * nfp + 1], qa_h[kc], l2, l3);
                mmabf(sfr[2 * nfp],     qa_l[kc], h0, h1);
                mmabf(sfr[2 * nfp + 1], qa_l[kc], h2, h3);
            }

        // ---- online max update ----
        float tm0 = -1e30f, tm1 = -1e30f;
#pragma unroll
        for (int nf = 0; nf < 8; nf++) {
            tm0 = fmaxf(tm0, fmaxf(sfr[nf][0], sfr[nf][1]));
            tm1 = fmaxf(tm1, fmaxf(sfr[nf][2], sfr[nf][3]));
        }
        tm0 = fmaxf(tm0, __shfl_xor_sync(0xffffffffu, tm0, 1));
        tm0 = fmaxf(tm0, __shfl_xor_sync(0xffffffffu, tm0, 2));
        tm1 = fmaxf(tm1, __shfl_xor_sync(0xffffffffu, tm1, 1));
        tm1 = fmaxf(tm1, __shfl_xor_sync(0xffffffffu, tm1, 2));
        float nM0 = fmaxf(M0, tm0), nM1 = fmaxf(M1, tm1);
        float sc0 = __expf(M0 - nM0), sc1 = __expf(M1 - nM1);
        M0 = nM0; M1 = nM1;
        sum0 *= sc0; sum1 *= sc1;
#pragma unroll
        for (int nf = 0; nf < 16; nf++) {
            o[nf][0] *= sc0; o[nf][1] *= sc0;
            o[nf][2] *= sc1; o[nf][3] *= sc1;
        }

        // ---- P = exp(S - M), pack bf16 hi/lo A-fragments ----
        uint32_t pah[4][4], pal[4][4];
#pragma unroll
        for (int kc = 0; kc < 4; kc++) {
            int fa = 2 * kc, fb = 2 * kc + 1;
            float p[8];
            p[0] = __expf(sfr[fa][0] - M0); p[1] = __expf(sfr[fa][1] - M0);
            p[2] = __expf(sfr[fa][2] - M1); p[3] = __expf(sfr[fa][3] - M1);
            p[4] = __expf(sfr[fb][0] - M0); p[5] = __expf(sfr[fb][1] - M0);
            p[6] = __expf(sfr[fb][2] - M1); p[7] = __expf(sfr[fb][3] - M1);
            sum0 += p[0] + p[1] + p[4] + p[5];
            sum1 += p[2] + p[3] + p[6] + p[7];
            float h[8], l[8];
#pragma unroll
            for (int i = 0; i < 8; i++) bsp(p[i], h[i], l[i]);
            pah[kc][0] = pk2(h[0], h[1]); pah[kc][1] = pk2(h[2], h[3]);
            pah[kc][2] = pk2(h[4], h[5]); pah[kc][3] = pk2(h[6], h[7]);
            pal[kc][0] = pk2(l[0], l[1]); pal[kc][1] = pk2(l[2], l[3]);
            pal[kc][2] = pk2(l[4], l[5]); pal[kc][3] = pk2(l[6], l[7]);
        }

        // ---- O += P.V^T (3-term), this warp's channel half ----
#pragma unroll
        for (int nfl = 0; nfl < 8; nfl++) {
            int nfp = hf * 8 + nfl;
#pragma unroll
            for (int kc = 0; kc < 4; kc++) {
                uint32_t boff = (uint32_t)(nfp * 16 + b_row) * 144 + (kc * 16 + b_kofs) * 2;
                uint32_t h0, h1, h2, h3, l0, l1, l2, l3;
                ldsm4(vb + boff, h0, h1, h2, h3);
                ldsm4(vb + VLOFF + boff, l0, l1, l2, l3);
                mmabf(o[2 * nfl],     pah[kc], h0, h1);
                mmabf(o[2 * nfl + 1], pah[kc], h2, h3);
                mmabf(o[2 * nfl],     pah[kc], l0, l1);
                mmabf(o[2 * nfl + 1], pah[kc], l2, l3);
                mmabf(o[2 * nfl],     pal[kc], h0, h1);
                mmabf(o[2 * nfl + 1], pal[kc], h2, h3);
            }
        }
        __syncthreads();
    }

    sum0 += __shfl_xor_sync(0xffffffffu, sum0, 1);
    sum0 += __shfl_xor_sync(0xffffffffu, sum0, 2);
    sum1 += __shfl_xor_sync(0xffffffffu, sum1, 1);
    sum1 += __shfl_xor_sync(0xffffffffu, sum1, 2);
    const float inv0 = 1.f / sum0, inv1 = 1.f / sum1;

    // ---- epilogue: O/sum -> g_ao[b][c][n] ----
    {
        float* aob = g_ao + (size_t)b * CCH * NTOK;
        const int r = lane >> 2, qd = lane & 3;
        const int n_g = q0 + rg * 16 + r;
#pragma unroll
        for (int nf = 0; nf < 16; nf++) {
            int c0 = hf * 128 + nf * 8 + qd * 2;
            aob[(size_t)c0 * NTOK + n_g]           = o[nf][0] * inv0;
            aob[(size_t)(c0 + 1) * NTOK + n_g]     = o[nf][1] * inv0;
            aob[(size_t)c0 * NTOK + n_g + 8]       = o[nf][2] * inv1;
            aob[(size_t)(c0 + 1) * NTOK + n_g + 8] = o[nf][3] * inv1;
        }
    }
}

// ---------------------------------------------------------------------------

extern "C" void kernel_launch(void* const* d_in, const int* in_sizes, int n_in,
                              void* d_out, int out_size)
{
    const float* x  = (const float*)d_in[0];
    const float* wq = (const float*)d_in[1];
    const float* bq = (const float*)d_in[2];
    const float* wk = (const float*)d_in[3];
    const float* bk = (const float*)d_in[4];
    const float* wv = (const float*)d_in[5];
    const float* bv = (const float*)d_in[6];
    const float* wo = (const float*)d_in[7];
    const float* bo = (const float*)d_in[8];
    float* out = (float*)d_out;

    cudaFuncSetAttribute(attn_mma_kernel, cudaFuncAttributeMaxDynamicSharedMemorySize,
                         ATTN_SMEM);

    dim3 blk(256);
    proj_kernel<DQK, DST_Q,  false><<<dim3(NTOK / 64, 1, BATCH), blk>>>(x, wq, bq, nullptr);
    proj_kernel<DQK, DST_K,  false><<<dim3(NTOK / 64, 1, BATCH), blk>>>(x, wk, bk, nullptr);
    proj_kernel<CCH, DST_V,  false><<<dim3(NTOK / 64, CCH / 64, BATCH), blk>>>(x, wv, bv, nullptr);
    attn_mma_kernel<<<dim3(NTOK / 128, BATCH), 512, ATTN_SMEM>>>();
    proj_kernel<CCH, DST_OUT, true><<<dim3(NTOK / 64, CCH / 64, BATCH), blk>>>(x, wo, bo, out);
}

// round 8
// speedup vs baseline: 1.4662x; 1.4662x over previous
#include <cuda_runtime.h>
#include <cuda_bf16.h>
#include <cstdint>
#include <cstddef>

// ---------------------------------------------------------------------------
// ComplexSpatialAttentionModule, sm_100 PTX: mma.sync m16n8k16 bf16 everywhere.
//  conv_x: x -> token-major bf16 hi/lo.  v/o projections: 3-term bf16 MMA GEMM.
//  attention: R6 8-warp flash kernel (known 377us), epilogue emits bf16 splits.
//  q/k projections: small SIMT f32x2 kernels.
// ---------------------------------------------------------------------------

#define BATCH 4
#define CCH   256
#define DQK   32
#define NTOK  4096

typedef unsigned long long u64t;

// ----- packed f32x2 helpers -----
#define FMA2(d, a, b, c) \
    asm("fma.rn.f32x2 %0, %1, %2, %3;" : "=l"(d) : "l"(a), "l"(b), "l"(c))
#define BCAST2(out, f) \
    asm("mov.b64 %0, {%1, %1};" : "=l"(out) : "r"(__float_as_uint(f)))
#define UNPACK2(lo, hi, v) \
    asm("mov.b64 {%0, %1}, %2;" : "=r"(lo), "=r"(hi) : "l"(v))
union F4U2 { float4 f; u64t u[2]; };
__device__ __forceinline__ float lo_f(u64t v) {
    unsigned int l, h; UNPACK2(l, h, v); return __uint_as_float(l);
}
__device__ __forceinline__ float hi_f(u64t v) {
    unsigned int l, h; UNPACK2(l, h, v); return __uint_as_float(h);
}

// ----- bf16 split/pack helpers -----
__device__ __forceinline__ uint32_t pk2(float lo, float hi) {
    uint32_t u;
    asm("cvt.rn.bf16x2.f32 %0, %1, %2;" : "=r"(u) : "f"(hi), "f"(lo));
    return u;
}
__device__ __forceinline__ void bsp(float x, float& h, float& l) {
    __nv_bfloat16 hb = __float2bfloat16(x);
    h = __bfloat162float(hb);
    l = x - h;
}

// ----- scratch (device globals) -----
__device__ __align__(16) uint32_t g_qh[BATCH * NTOK * 16];
__device__ __align__(16) uint32_t g_ql[BATCH * NTOK * 16];
__device__ __align__(16) uint32_t g_kh[BATCH * NTOK * 16];
__device__ __align__(16) uint32_t g_kl[BATCH * NTOK * 16];
__device__ __align__(16) uint32_t g_vh[BATCH * CCH * (NTOK / 2)];   // [b][c][n/2]
__device__ __align__(16) uint32_t g_vl[BATCH * CCH * (NTOK / 2)];
__device__ __align__(16) uint32_t g_xth[BATCH * NTOK * (CCH / 2)];  // [b][n][c/2]
__device__ __align__(16) uint32_t g_xtl[BATCH * NTOK * (CCH / 2)];
__device__ __align__(16) uint32_t g_aoh[BATCH * NTOK * (CCH / 2)];  // [b][n][c/2]
__device__ __align__(16) uint32_t g_aol[BATCH * NTOK * (CCH / 2)];

// ---------------------------------------------------------------------------
// conv_x: x fp32 [b][c][n] -> token-major bf16 hi/lo words [b][n][c/2]
// ---------------------------------------------------------------------------
__global__ __launch_bounds__(256) void conv_x_kernel(const float* __restrict__ x)
{
    __shared__ float xs[64][65];
    const int b = blockIdx.z;
    const int c0 = blockIdx.y * 64, n0 = blockIdx.x * 64;
    const int t = threadIdx.x;
#pragma unroll
    for (int i = 0; i < 16; i++) {
        int e = t + i * 256;
        int c = e >> 6, n = e & 63;
        xs[c][n] = x[((size_t)b * CCH + c0 + c) * NTOK + n0 + n];
    }
    __syncthreads();
#pragma unroll
    for (int i = 0; i < 8; i++) {
        int e = t + i * 256;
        int nl = e >> 5, cw = e & 31;
        float f0 = xs[2 * cw][nl], f1 = xs[2 * cw + 1][nl];
        float h0, l0, h1, l1;
        bsp(f0, h0, l0); bsp(f1, h1, l1);
        size_t widx = ((size_t)b * NTOK + n0 + nl) * (CCH / 2) + (c0 >> 1) + cw;
        g_xth[widx] = pk2(h0, h1);
        g_xtl[widx] = pk2(l0, l1);
    }
}

// ---------------------------------------------------------------------------
// q/k projection (SIMT f32x2): out token-major bf16 hi/lo [b][n][16 words]
// ---------------------------------------------------------------------------
template <int DST>   // 0 = Q, 1 = K
__global__ __launch_bounds__(256) void qk_proj_kernel(
    const float* __restrict__ x, const float* __restrict__ w,
    const float* __restrict__ bias)
{
    constexpr int IC = CCH;
    __shared__ float wt[16][64];
    __shared__ float xs[16][64];
    const int b = blockIdx.z;
    const float* xb = x + (size_t)b * IC * NTOK;
    const int ntile = blockIdx.x * 64;
    const int t  = threadIdx.x;
    const int og = t & 15, ng = t >> 4;
    const int o0 = og * 4, n0 = ng * 4;

    u64t acc2[4][2];
#pragma unroll
    for (int i = 0; i < 4; i++) { acc2[i][0] = 0ull; acc2[i][1] = 0ull; }

    for (int ct = 0; ct < IC; ct += 16) {
#pragma unroll
        for (int i = 0; i < 4; i++) {
            int idx = t + i * 256;
            int o = idx >> 4, cc = idx & 15;
            float val = 0.f;
            if (o < DQK) val = w[(size_t)o * IC + ct + cc];
            wt[cc][o] = val;
        }
#pragma unroll
        for (int i = 0; i < 4; i++) {
            int idx = t + i * 256;
            int cc = idx >> 6, n = idx & 63;
            xs[cc][n] = xb[(size_t)(ct + cc) * NTOK + ntile + n];
        }
        __syncthreads();
#pragma unroll
        for (int cc = 0; cc < 16; cc++) {
            F4U2 w4, x4;
            w4.f = *(const float4*)&wt[cc][o0];
            x4.f = *(const float4*)&xs[cc][n0];
            float wv4[4] = {w4.f.x, w4.f.y, w4.f.z, w4.f.w};
            u64t wb[4];
#pragma unroll
            for (int oi = 0; oi < 4; oi++) BCAST2(wb[oi], wv4[oi]);
#pragma unroll
            for (int oi = 0; oi < 4; oi++) {
                FMA2(acc2[oi][0], wb[oi], x4.u[0], acc2[oi][0]);
                FMA2(acc2[oi][1], wb[oi], x4.u[1], acc2[oi][1]);
            }
        }
        __syncthreads();
    }

    if (o0 < DQK) {
        uint32_t* gh = ((DST == 0) ? g_qh : g_kh) + (size_t)b * NTOK * 16;
        uint32_t* gl = ((DST == 0) ? g_ql : g_kl) + (size_t)b * NTOK * 16;
        float bv[4] = {bias[o0], bias[o0 + 1], bias[o0 + 2], bias[o0 + 3]};
        float vals[4][4];
#pragma unroll
        for (int oi = 0; oi < 4; oi++) {
            vals[oi][0] = lo_f(acc2[oi][0]); vals[oi][1] = hi_f(acc2[oi][0]);
            vals[oi][2] = lo_f(acc2[oi][1]); vals[oi][3] = hi_f(acc2[oi][1]);
        }
#pragma unroll
        for (int ni = 0; ni < 4; ni++) {
            float h[4], l[4];
#pragma unroll
            for (int oi = 0; oi < 4; oi++) bsp(vals[oi][ni] + bv[oi], h[oi], l[oi]);
            size_t widx = (size_t)(ntile + n0 + ni) * 16 + (o0 >> 1);
            *(uint2*)(gh + widx) = make_uint2(pk2(h[0], h[1]), pk2(h[2], h[3]));
            *(uint2*)(gl + widx) = make_uint2(pk2(l[0], l[1]), pk2(l[2], l[3]));
        }
    }
}

// ---------------------------------------------------------------------------
// mma / ldmatrix / cp.async helpers
// ---------------------------------------------------------------------------
__device__ __forceinline__ uint32_t smem_u32(const void* p) {
    uint32_t a;
    asm("{ .reg .u64 t; cvta.to.shared.u64 t, %1; cvt.u32.u64 %0, t; }"
        : "=r"(a) : "l"(p));
    return a;
}
__device__ __forceinline__ void ldsm4(uint32_t addr, uint32_t& r0, uint32_t& r1,
                                      uint32_t& r2, uint32_t& r3) {
    asm volatile("ldmatrix.sync.aligned.m8n8.x4.shared.b16 {%0,%1,%2,%3}, [%4];"
                 : "=r"(r0), "=r"(r1), "=r"(r2), "=r"(r3) : "r"(addr));
}
__device__ __forceinline__ void mmabf(float* d, const uint32_t* a,
                                      uint32_t b0, uint32_t b1) {
    asm volatile(
        "mma.sync.aligned.m16n8k16.row.col.f32.bf16.bf16.f32 "
        "{%0,%1,%2,%3}, {%4,%5,%6,%7}, {%8,%9}, {%0,%1,%2,%3};"
        : "+f"(d[0]), "+f"(d[1]), "+f"(d[2]), "+f"(d[3])
        : "r"(a[0]), "r"(a[1]), "r"(a[2]), "r"(a[3]), "r"(b0), "r"(b1));
}
__device__ __forceinline__ void cp16(uint32_t dst, const void* src) {
    asm volatile("cp.async.cg.shared.global [%0], [%1], 16;"
                 :: "r"(dst), "l"(src) : "memory");
}
#define CP_COMMIT() asm volatile("cp.async.commit_group;" ::: "memory")
#define CP_WAIT1()  asm volatile("cp.async.wait_group 1;" ::: "memory")

// ---------------------------------------------------------------------------
// mma_proj: out[o][n] = sum_c W[o][c] in[c][n] (+bias, +residual or ->bf16)
// CTA = 128 o x 128 n, 8 warps (warp = 16 o-rows x 128 n). 3-term bf16.
// SMEM: AH 0, AL 18432, BH 36864, BL 55296; rows stride 144B (64c x 2B + pad).
// ---------------------------------------------------------------------------
#define MP_AH 0
#define MP_AL 18432
#define MP_BH 36864
#define MP_BL 55296
#define MP_SMEM 73728

template <bool ISV>
__global__ __launch_bounds__(256) void mma_proj_kernel(
    const float* __restrict__ wparam, const float* __restrict__ bias,
    const float* __restrict__ xres, float* __restrict__ outparam)
{
    extern __shared__ __align__(16) char smem[];
    const int t = threadIdx.x, lane = t & 31, w = t >> 5;
    const int b = blockIdx.z;
    const int ntile = blockIdx.x * 128, otile = blockIdx.y * 128;
    const uint32_t sb = smem_u32(smem);

    const uint32_t* gbh = (ISV ? g_xth : g_aoh) + (size_t)b * NTOK * (CCH / 2);
    const uint32_t* gbl = (ISV ? g_xtl : g_aol) + (size_t)b * NTOK * (CCH / 2);

    float acc[16][4];
#pragma unroll
    for (int i = 0; i < 16; i++)
#pragma unroll
        for (int j = 0; j < 4; j++) acc[i][j] = 0.f;

    const int a_row  = (lane & 7) + (lane & 8);
    const int a_kofs = (lane & 16) ? 8 : 0;
    const int b_row  = (lane & 7) + ((lane & 16) ? 8 : 0);
    const int b_kofs = (lane & 8);

    for (int cc = 0; cc < CCH; cc += 64) {
        __syncthreads();
        // A tile: W[otile..+128][cc..+64] fp32 -> split bf16 hi/lo
#pragma unroll
        for (int i = 0; i < 16; i++) {
            int e = t + i * 256;                  // 4096 word-pairs
            int orow = e >> 5, cw = e & 31;
            float2 wv = *(const float2*)&wparam[(size_t)(otile + orow) * CCH + cc + 2 * cw];
            float h0, l0, h1, l1;
            bsp(wv.x, h0, l0); bsp(wv.y, h1, l1);
            *(uint32_t*)(smem + MP_AH + orow * 144 + cw * 4) = pk2(h0, h1);
            *(uint32_t*)(smem + MP_AL + orow * 144 + cw * 4) = pk2(l0, l1);
        }
        // B tile: token-major bf16 words [n][c/2]
#pragma unroll
        for (int i = 0; i < 16; i++) {
            int e = t + i * 256;
            int nr = e >> 5, cw = e & 31;
            size_t gidx = (size_t)(ntile + nr) * (CCH / 2) + (cc >> 1) + cw;
            *(uint32_t*)(smem + MP_BH + nr * 144 + cw * 4) = gbh[gidx];
            *(uint32_t*)(smem + MP_BL + nr * 144 + cw * 4) = gbl[gidx];
        }
        __syncthreads();

#pragma unroll
        for (int kc = 0; kc < 4; kc++) {
            uint32_t aoff = (uint32_t)(w * 16 + a_row) * 144 + (kc * 16 + a_kofs) * 2;
            uint32_t ah[4], al[4];
            ldsm4(sb + MP_AH + aoff, ah[0], ah[1], ah[2], ah[3]);
            ldsm4(sb + MP_AL + aoff, al[0], al[1], al[2], al[3]);
#pragma unroll
            for (int nfp = 0; nfp < 8; nfp++) {
                uint32_t boff = (uint32_t)(nfp * 16 + b_row) * 144 + (kc * 16 + b_kofs) * 2;
                uint32_t h0, h1, h2, h3, l0, l1, l2, l3;
                ldsm4(sb + MP_BH + boff, h0, h1, h2, h3);
                ldsm4(sb + MP_BL + boff, l0, l1, l2, l3);
                mmabf(acc[2 * nfp],     ah, h0, h1);
                mmabf(acc[2 * nfp + 1], ah, h2, h3);
                mmabf(acc[2 * nfp],     ah, l0, l1);
                mmabf(acc[2 * nfp + 1], ah, l2, l3);
                mmabf(acc[2 * nfp],     al, h0, h1);
                mmabf(acc[2 * nfp + 1], al, h2, h3);
            }
        }
    }

    const int r = lane >> 2, nq = (lane & 3) * 2;
    const int oA = otile + w * 16 + r;
    const int oB = oA + 8;
    const float bvA = bias[oA], bvB = bias[oB];

    if (ISV) {
        uint32_t* vh = g_vh + ((size_t)b * CCH) * (NTOK / 2);
        uint32_t* vl = g_vl + ((size_t)b * CCH) * (NTOK / 2);
#pragma unroll
        for (int nf = 0; nf < 16; nf++) {
            int n = ntile + nf * 8 + nq;
            float h0, l0, h1, l1;
            bsp(acc[nf][0] + bvA, h0, l0); bsp(acc[nf][1] + bvA, h1, l1);
            size_t wA = (size_t)oA * (NTOK / 2) + (n >> 1);
            vh[wA] = pk2(h0, h1); vl[wA] = pk2(l0, l1);
            bsp(acc[nf][2] + bvB, h0, l0); bsp(acc[nf][3] + bvB, h1, l1);
            size_t wB = (size_t)oB * (NTOK / 2) + (n >> 1);
            vh[wB] = pk2(h0, h1); vl[wB] = pk2(l0, l1);
        }
    } else {
        float* ob = outparam + (size_t)b * CCH * NTOK;
        const float* rb = xres + (size_t)b * CCH * NTOK;
#pragma unroll
        for (int nf = 0; nf < 16; nf++) {
            int n = ntile + nf * 8 + nq;
            size_t iA = (size_t)oA * NTOK + n;
            size_t iB = (size_t)oB * NTOK + n;
            float2 rA = *(const float2*)&rb[iA];
            float2 rB = *(const float2*)&rb[iB];
            float2 oAv, oBv;
            oAv.x = acc[nf][0] + bvA + rA.x; oAv.y = acc[nf][1] + bvA + rA.y;
            oBv.x = acc[nf][2] + bvB + rB.x; oBv.y = acc[nf][3] + bvB + rB.y;
            *(float2*)&ob[iA] = oAv;
            *(float2*)&ob[iB] = oBv;
        }
    }
}

// ---------------------------------------------------------------------------
// Attention (R6 8-warp kernel; epilogue emits bf16 hi/lo token-major)
// ---------------------------------------------------------------------------
#define SM_QH 0
#define SM_QL 10240
#define KB0   20480
#define KB1   30720
#define KLOFF 5120
#define VB0   40960
#define VB1   114688
#define VLOFF 36864
#define ATTN_SMEM 188416

__device__ __forceinline__ void issue_tile(uint32_t sb, int buf, int nc, int t,
    const uint4* gkh, const uint4* gkl, const uint4* gvh, const uint4* gvl)
{
    const uint32_t kb = sb + (buf ? KB1 : KB0);
    const uint32_t vb = sb + (buf ? VB1 : VB0);
    const int krow = t >> 2, kq = t & 3;
    cp16(kb + krow * 80 + kq * 16,         gkh + (size_t)(nc + krow) * 4 + kq);
    cp16(kb + KLOFF + krow * 80 + kq * 16, gkl + (size_t)(nc + krow) * 4 + kq);
    const int vr = t >> 3, vq = t & 7;
    const int nq = nc >> 3;
#pragma unroll
    for (int i = 0; i < 8; i++) {
        int row = vr + i * 32;
        cp16(vb + row * 144 + vq * 16,         gvh + (size_t)row * 512 + nq + vq);
        cp16(vb + VLOFF + row * 144 + vq * 16, gvl + (size_t)row * 512 + nq + vq);
    }
}

__global__ __launch_bounds__(256) void attn_mma_kernel()
{
    extern __shared__ __align__(16) char smem[];
    const int t = threadIdx.x, lane = t & 31, w = t >> 5;
    const int b = blockIdx.y, q0 = blockIdx.x * 128;
    const uint32_t sb = smem_u32(smem);

    const uint4* gkh = (const uint4*)g_kh + (size_t)b * NTOK * 4;
    const uint4* gkl = (const uint4*)g_kl + (size_t)b * NTOK * 4;
    const uint4* gvh = (const uint4*)g_vh + (size_t)b * CCH * 512;
    const uint4* gvl = (const uint4*)g_vl + (size_t)b * CCH * 512;

    {
        int row = t >> 1;
        size_t gidx = ((size_t)b * NTOK + q0 + row) * 4 + (t & 1) * 2;
        const uint4* sh = (const uint4*)g_qh + gidx;
        const uint4* sl = (const uint4*)g_ql + gidx;
        uint4* dh = (uint4*)(smem + SM_QH + row * 80 + (t & 1) * 32);
        uint4* dl = (uint4*)(smem + SM_QL + row * 80 + (t & 1) * 32);
        dh[0] = sh[0]; dh[1] = sh[1];
        dl[0] = sl[0]; dl[1] = sl[1];
    }
    issue_tile(sb, 0, 0, t, gkh, gkl, gvh, gvl);
    CP_COMMIT();
    __syncthreads();

    const int a_row  = (lane & 7) + (lane & 8);
    const int a_kofs = (lane & 16) ? 8 : 0;
    const int b_row  = (lane & 7) + ((lane & 16) ? 8 : 0);
    const int b_kofs = (lane & 8);

    uint32_t qa_h[2][4], qa_l[2][4];
#pragma unroll
    for (int kc = 0; kc < 2; kc++) {
        uint32_t byteoff = (uint32_t)(w * 16 + a_row) * 80 + (kc * 16 + a_kofs) * 2;
        ldsm4(sb + SM_QH + byteoff, qa_h[kc][0], qa_h[kc][1], qa_h[kc][2], qa_h[kc][3]);
        ldsm4(sb + SM_QL + byteoff, qa_l[kc][0], qa_l[kc][1], qa_l[kc][2], qa_l[kc][3]);
    }

    float M0 = -1e30f, M1 = -1e30f, sum0 = 0.f, sum1 = 0.f;
    float o[32][4];
#pragma unroll
    for (int i = 0; i < 32; i++)
#pragma unroll
        for (int j = 0; j < 4; j++) o[i][j] = 0.f;

    for (int ti = 0; ti < 64; ti++) {
        if (ti < 63) issue_tile(sb, (ti + 1) & 1, (ti + 1) * 64, t, gkh, gkl, gvh, gvl);
        CP_COMMIT();
        CP_WAIT1();
        __syncthreads();

        const uint32_t kb = sb + ((ti & 1) ? KB1 : KB0);
        const uint32_t vb = sb + ((ti & 1) ? VB1 : VB0);

        float sfr[8][4];
#pragma unroll
        for (int i = 0; i < 8; i++)
#pragma unroll
            for (int j = 0; j < 4; j++) sfr[i][j] = 0.f;

#pragma unroll
        for (int nfp = 0; nfp < 4; nfp++)
#pragma unroll
            for (int kc = 0; kc < 2; kc++) {
                uint32_t boff = (uint32_t)(nfp * 16 + b_row) * 80 + (kc * 16 + b_kofs) * 2;
                uint32_t h0, h1, h2, h3, l0, l1, l2, l3;
                ldsm4(kb + boff, h0, h1, h2, h3);
                ldsm4(kb + KLOFF + boff, l0, l1, l2, l3);
                mmabf(sfr[2 * nfp],     qa_h[kc], h0, h1);
                mmabf(sfr[2 * nfp + 1], qa_h[kc], h2, h3);
                mmabf(sfr[2 * nfp],     qa_h[kc], l0, l1);
                mmabf(sfr[2 * nfp + 1], qa_h[kc], l2, l3);
                mmabf(sfr[2 * nfp],     qa_l[kc], h0, h1);
                mmabf(sfr[2 * nfp + 1], qa_l[kc], h2, h3);
            }

        float tm0 = -1e30f, tm1 = -1e30f;
#pragma unroll
        for (int nf = 0; nf < 8; nf++) {
            tm0 = fmaxf(tm0, fmaxf(sfr[nf][0], sfr[nf][1]));
            tm1 = fmaxf(tm1, fmaxf(sfr[nf][2], sfr[nf][3]));
        }
        tm0 = fmaxf(tm0, __shfl_xor_sync(0xffffffffu, tm0, 1));
        tm0 = fmaxf(tm0, __shfl_xor_sync(0xffffffffu, tm0, 2));
        tm1 = fmaxf(tm1, __shfl_xor_sync(0xffffffffu, tm1, 1));
        tm1 = fmaxf(tm1, __shfl_xor_sync(0xffffffffu, tm1, 2));
        float nM0 = fmaxf(M0, tm0), nM1 = fmaxf(M1, tm1);
        float sc0 = __expf(M0 - nM0), sc1 = __expf(M1 - nM1);
        M0 = nM0; M1 = nM1;
        sum0 *= sc0; sum1 *= sc1;
#pragma unroll
        for (int nf = 0; nf < 32; nf++) {
            o[nf][0] *= sc0; o[nf][1] *= sc0;
            o[nf][2] *= sc1; o[nf][3] *= sc1;
        }

        uint32_t pah[4][4], pal[4][4];
#pragma unroll
        for (int kc = 0; kc < 4; kc++) {
            int fa = 2 * kc, fb = 2 * kc + 1;
            float p[8];
            p[0] = __expf(sfr[fa][0] - M0); p[1] = __expf(sfr[fa][1] - M0);
            p[2] = __expf(sfr[fa][2] - M1); p[3] = __expf(sfr[fa][3] - M1);
            p[4] = __expf(sfr[fb][0] - M0); p[5] = __expf(sfr[fb][1] - M0);
            p[6] = __expf(sfr[fb][2] - M1); p[7] = __expf(sfr[fb][3] - M1);
            sum0 += p[0] + p[1] + p[4] + p[5];
            sum1 += p[2] + p[3] + p[6] + p[7];
            float h[8], l[8];
#pragma unroll
            for (int i = 0; i < 8; i++) bsp(p[i], h[i], l[i]);
            pah[kc][0] = pk2(h[0], h[1]); pah[kc][1] = pk2(h[2], h[3]);
            pah[kc][2] = pk2(h[4], h[5]); pah[kc][3] = pk2(h[6], h[7]);
            pal[kc][0] = pk2(l[0], l[1]); pal[kc][1] = pk2(l[2], l[3]);
            pal[kc][2] = pk2(l[4], l[5]); pal[kc][3] = pk2(l[6], l[7]);
        }

#pragma unroll
        for (int nfp = 0; nfp < 16; nfp++)
#pragma unroll
            for (int kc = 0; kc < 4; kc++) {
                uint32_t boff = (uint32_t)(nfp * 16 + b_row) * 144 + (kc * 16 + b_kofs) * 2;
                uint32_t h0, h1, h2, h3, l0, l1, l2, l3;
                ldsm4(vb + boff, h0, h1, h2, h3);
                ldsm4(vb + VLOFF + boff, l0, l1, l2, l3);
                mmabf(o[2 * nfp],     pah[kc], h0, h1);
                mmabf(o[2 * nfp + 1], pah[kc], h2, h3);
                mmabf(o[2 * nfp],     pah[kc], l0, l1);
                mmabf(o[2 * nfp + 1], pah[kc], l2, l3);
                mmabf(o[2 * nfp],     pal[kc], h0, h1);
                mmabf(o[2 * nfp + 1], pal[kc], h2, h3);
            }
        __syncthreads();
    }

    sum0 += __shfl_xor_sync(0xffffffffu, sum0, 1);
    sum0 += __shfl_xor_sync(0xffffffffu, sum0, 2);
    sum1 += __shfl_xor_sync(0xffffffffu, sum1, 1);
    sum1 += __shfl_xor_sync(0xffffffffu, sum1, 2);
    const float inv0 = 1.f / sum0, inv1 = 1.f / sum1;

    // ---- epilogue: bf16 hi/lo token-major words [b][n][c/2] ----
    {
        uint32_t* aoh = g_aoh + (size_t)b * NTOK * (CCH / 2);
        uint32_t* aol = g_aol + (size_t)b * NTOK * (CCH / 2);
        const int r = lane >> 2, qd = lane & 3;
        const int n_g = q0 + w * 16 + r;
#pragma unroll
        for (int nf = 0; nf < 32; nf++) {
            int c0 = nf * 8 + qd * 2;
            float h0, l0, h1, l1;
            bsp(o[nf][0] * inv0, h0, l0); bsp(o[nf][1] * inv0, h1, l1);
            size_t a0 = (size_t)n_g * (CCH / 2) + (c0 >> 1);
            aoh[a0] = pk2(h0, h1); aol[a0] = pk2(l0, l1);
            bsp(o[nf][2] * inv1, h0, l0); bsp(o[nf][3] * inv1, h1, l1);
            size_t a1 = (size_t)(n_g + 8) * (CCH / 2) + (c0 >> 1);
            aoh[a1] = pk2(h0, h1); aol[a1] = pk2(l0, l1);
        }
    }
}

// ---------------------------------------------------------------------------

extern "C" void kernel_launch(void* const* d_in, const int* in_sizes, int n_in,
                              void* d_out, int out_size)
{
    const float* x  = (const float*)d_in[0];
    const float* wq = (const float*)d_in[1];
    const float* bq = (const float*)d_in[2];
    const float* wk = (const float*)d_in[3];
    const float* bk = (const float*)d_in[4];
    const float* wv = (const float*)d_in[5];
    const float* bv = (const float*)d_in[6];
    const float* wo = (const float*)d_in[7];
    const float* bo = (const float*)d_in[8];
    float* out = (float*)d_out;

    cudaFuncSetAttribute(attn_mma_kernel, cudaFuncAttributeMaxDynamicSharedMemorySize,
                         ATTN_SMEM);
    cudaFuncSetAttribute(mma_proj_kernel<true>, cudaFuncAttributeMaxDynamicSharedMemorySize,
                         MP_SMEM);
    cudaFuncSetAttribute(mma_proj_kernel<false>, cudaFuncAttributeMaxDynamicSharedMemorySize,
                         MP_SMEM);

    conv_x_kernel<<<dim3(NTOK / 64, CCH / 64, BATCH), 256>>>(x);
    qk_proj_kernel<0><<<dim3(NTOK / 64, 1, BATCH), 256>>>(x, wq, bq);
    qk_proj_kernel<1><<<dim3(NTOK / 64, 1, BATCH), 256>>>(x, wk, bk);
    mma_proj_kernel<true><<<dim3(NTOK / 128, CCH / 128, BATCH), 256, MP_SMEM>>>(
        wv, bv, nullptr, nullptr);
    attn_mma_kernel<<<dim3(NTOK / 128, BATCH), 256, ATTN_SMEM>>>();
    mma_proj_kernel<false><<<dim3(NTOK / 128, CCH / 128, BATCH), 256, MP_SMEM>>>(
        wo, bo, x, out);
}